// round 15
// baseline (speedup 1.0000x reference)
#include <cuda_runtime.h>
#include <cstdint>

#define MAXN 100352
#define Df 64
#define Hf 128

// scratch: node flow accumulator (25.7 MB) + index-dtype flag
__device__ float g_flow[(size_t)MAXN * Df];
__device__ int g_idx64;

// ---------------------------------------------------------------------------
// Probe: decide whether edge_index is int64 or int32.
// If int64 (little-endian, values < 2^31), every odd 32-bit word is 0.
// With int32 random indices in [0, 100000), 256 sampled odd words being all
// zero has probability ~ (1e-5)^256 ~ 0.
// ---------------------------------------------------------------------------
__global__ void probe_kernel(const int* __restrict__ idx) {
    __shared__ int any;
    if (threadIdx.x == 0) any = 0;
    __syncthreads();
    int v = idx[threadIdx.x * 2 + 1];
    if (v != 0) atomicOr(&any, 1);
    __syncthreads();
    if (threadIdx.x == 0) g_idx64 = (any == 0) ? 1 : 0;
}

// ---------------------------------------------------------------------------
// Scatter: each thread handles one (edge, 16B-quarter) pair and issues two
// vector reductions (past & future endpoints). red.global.add.v4.f32 keeps
// the data in L2 (flow buffer is 25.6 MB, fits the 126 MB L2).
// ---------------------------------------------------------------------------
__global__ void scatter_kernel(const int* __restrict__ idx,
                               const float4* __restrict__ attr,
                               long long E) {
    long long item = (long long)blockIdx.x * blockDim.x + threadIdx.x;
    if (item >= E * 16) return;
    long long e = item >> 4;
    int q = (int)(item & 15);

    float4 v = attr[e * 16 + q];

    int p, f;
    if (g_idx64) {
        const long long* i64 = (const long long*)idx;
        p = (int)i64[e];
        f = (int)i64[E + e];
    } else {
        p = idx[e];
        f = idx[E + e];
    }

    float* dst1 = g_flow + (long long)f * Df + q * 4;
    float* dst2 = g_flow + (long long)p * Df + q * 4;
    asm volatile("red.global.add.v4.f32 [%0], {%1,%2,%3,%4};"
                 :: "l"(dst1), "f"(v.x), "f"(v.y), "f"(v.z), "f"(v.w) : "memory");
    asm volatile("red.global.add.v4.f32 [%0], {%1,%2,%3,%4};"
                 :: "l"(dst2), "f"(v.x), "f"(v.y), "f"(v.z), "f"(v.w) : "memory");
}

// ---------------------------------------------------------------------------
// MLP: out = relu(flow @ W1 + b1) @ W2 + b2, thread-per-node.
// W1 transposed into smem with row stride 68 (float4-aligned, reduces STS
// transpose conflicts to 4-way and LDS128 conflicts to 4-way).
// flow row (64 regs) + output accumulators (64 regs) live in registers.
// All weight reads are warp-broadcast LDS128.
// ---------------------------------------------------------------------------
#define W1T_STRIDE 68

__global__ __launch_bounds__(128, 3)
void mlp_kernel(const float* __restrict__ W1, const float* __restrict__ b1,
                const float* __restrict__ W2, const float* __restrict__ b2,
                float* __restrict__ out, int N) {
    extern __shared__ float smem[];
    float* sW1T = smem;                       // [H][W1T_STRIDE]
    float* sW2  = sW1T + Hf * W1T_STRIDE;     // [H][D]
    float* sb1  = sW2 + Hf * Df;              // [H]
    float* sb2  = sb1 + Hf;                   // [D]

    int tid = threadIdx.x;
    // W1 is [D][H] row-major; thread t owns hidden unit j=t, reads its column
    // (coalesced across threads at fixed k).
    #pragma unroll 4
    for (int k = 0; k < Df; k++)
        sW1T[tid * W1T_STRIDE + k] = W1[k * Hf + tid];
    for (int i = tid; i < Hf * Df; i += 128)
        sW2[i] = W2[i];
    if (tid < Hf) sb1[tid] = b1[tid];
    if (tid < Df) sb2[tid] = b2[tid];
    __syncthreads();

    int node = blockIdx.x * 128 + tid;
    if (node >= N) return;

    float4 fr[16];
    const float4* frow = (const float4*)(g_flow + (long long)node * Df);
    #pragma unroll
    for (int i = 0; i < 16; i++) fr[i] = frow[i];

    float acc[Df];
    #pragma unroll
    for (int i = 0; i < Df; i++) acc[i] = sb2[i];

    for (int j = 0; j < Hf; j++) {
        float h = sb1[j];
        const float4* w1 = (const float4*)(sW1T + j * W1T_STRIDE);
        #pragma unroll
        for (int i = 0; i < 16; i++) {
            float4 w = w1[i];
            h += fr[i].x * w.x + fr[i].y * w.y + fr[i].z * w.z + fr[i].w * w.w;
        }
        h = fmaxf(h, 0.0f);
        const float4* w2 = (const float4*)(sW2 + j * Df);
        #pragma unroll
        for (int i = 0; i < 16; i++) {
            float4 w = w2[i];
            acc[i * 4 + 0] += h * w.x;
            acc[i * 4 + 1] += h * w.y;
            acc[i * 4 + 2] += h * w.z;
            acc[i * 4 + 3] += h * w.w;
        }
    }

    float4* orow = (float4*)(out + (long long)node * Df);
    #pragma unroll
    for (int i = 0; i < 16; i++)
        orow[i] = make_float4(acc[i * 4], acc[i * 4 + 1], acc[i * 4 + 2], acc[i * 4 + 3]);
}

// ---------------------------------------------------------------------------
extern "C" void kernel_launch(void* const* d_in, const int* in_sizes, int n_in,
                              void* d_out, int out_size) {
    const int*   idx  = (const int*)d_in[0];
    const float* attr = (const float*)d_in[1];
    // num_nodes may or may not be materialized as an input
    int base = (n_in >= 7) ? 3 : 2;
    const float* W1 = (const float*)d_in[base + 0];
    const float* b1 = (const float*)d_in[base + 1];
    const float* W2 = (const float*)d_in[base + 2];
    const float* b2 = (const float*)d_in[base + 3];

    long long E = (long long)in_sizes[1] / Df;   // edge_attr is [E, 64]
    int N = out_size / Df;                        // output is [N, 64]

    void* flow_ptr = nullptr;
    cudaGetSymbolAddress(&flow_ptr, g_flow);
    cudaMemsetAsync(flow_ptr, 0, (size_t)N * Df * sizeof(float));

    probe_kernel<<<1, 256>>>(idx);

    long long total = E * 16;
    int blk = 256;
    unsigned nb = (unsigned)((total + blk - 1) / blk);
    scatter_kernel<<<nb, blk>>>(idx, (const float4*)attr, E);

    size_t smem = (size_t)(Hf * W1T_STRIDE + Hf * Df + Hf + Df) * sizeof(float);
    cudaFuncSetAttribute(mlp_kernel, cudaFuncAttributeMaxDynamicSharedMemorySize, (int)smem);
    mlp_kernel<<<(N + 127) / 128, 128, smem>>>(W1, b1, W2, b2, (float*)d_out, N);
}

// round 16
// speedup vs baseline: 1.5503x; 1.5503x over previous
#include <cuda_runtime.h>
#include <cstdint>

#define MAXN 100352
#define Df 64
#define Hf 128

// scratch: node flow accumulator (25.7 MB) + index-dtype flag
__device__ float g_flow[(size_t)MAXN * Df];
__device__ int g_idx64;

// ---------------------------------------------------------------------------
// Probe: decide whether edge_index is int64 or int32.
// If int64 (little-endian, values < 2^31), every odd 32-bit word is 0.
// With int32 random indices in [0, 100000), 256 sampled odd words being all
// zero has probability ~ (1e-5)^256 ~ 0.
// ---------------------------------------------------------------------------
__global__ void probe_kernel(const int* __restrict__ idx) {
    __shared__ int any;
    if (threadIdx.x == 0) any = 0;
    __syncthreads();
    int v = idx[threadIdx.x * 2 + 1];
    if (v != 0) atomicOr(&any, 1);
    __syncthreads();
    if (threadIdx.x == 0) g_idx64 = (any == 0) ? 1 : 0;
}

// ---------------------------------------------------------------------------
// Scatter: each thread handles one (edge, 16B-quarter) pair and issues two
// vector reductions (past & future endpoints). red.global.add.v4.f32 keeps
// the data in L2 (flow buffer is 25.6 MB, fits the 126 MB L2).
// ---------------------------------------------------------------------------
__global__ void scatter_kernel(const int* __restrict__ idx,
                               const float4* __restrict__ attr,
                               long long E) {
    long long item = (long long)blockIdx.x * blockDim.x + threadIdx.x;
    if (item >= E * 16) return;
    long long e = item >> 4;
    int q = (int)(item & 15);

    float4 v = attr[e * 16 + q];

    int p, f;
    if (g_idx64) {
        const long long* i64 = (const long long*)idx;
        p = (int)i64[e];
        f = (int)i64[E + e];
    } else {
        p = idx[e];
        f = idx[E + e];
    }

    float* dst1 = g_flow + (long long)f * Df + q * 4;
    float* dst2 = g_flow + (long long)p * Df + q * 4;
    asm volatile("red.global.add.v4.f32 [%0], {%1,%2,%3,%4};"
                 :: "l"(dst1), "f"(v.x), "f"(v.y), "f"(v.z), "f"(v.w) : "memory");
    asm volatile("red.global.add.v4.f32 [%0], {%1,%2,%3,%4};"
                 :: "l"(dst2), "f"(v.x), "f"(v.y), "f"(v.z), "f"(v.w) : "memory");
}

// ---------------------------------------------------------------------------
// MLP: out = relu(flow @ W1 + b1) @ W2 + b2, thread-per-node.
// W1 transposed into smem with row stride 68 (float4-aligned, reduces STS
// transpose conflicts to 4-way and LDS128 conflicts to 4-way).
// flow row (64 regs) + output accumulators (64 regs) live in registers.
// All weight reads are warp-broadcast LDS128.
// ---------------------------------------------------------------------------
#define W1T_STRIDE 68

__global__ __launch_bounds__(128, 3)
void mlp_kernel(const float* __restrict__ W1, const float* __restrict__ b1,
                const float* __restrict__ W2, const float* __restrict__ b2,
                float* __restrict__ out, int N) {
    extern __shared__ float smem[];
    float* sW1T = smem;                       // [H][W1T_STRIDE]
    float* sW2  = sW1T + Hf * W1T_STRIDE;     // [H][D]
    float* sb1  = sW2 + Hf * Df;              // [H]
    float* sb2  = sb1 + Hf;                   // [D]

    int tid = threadIdx.x;
    // W1 is [D][H] row-major; thread t owns hidden unit j=t, reads its column
    // (coalesced across threads at fixed k).
    #pragma unroll 4
    for (int k = 0; k < Df; k++)
        sW1T[tid * W1T_STRIDE + k] = W1[k * Hf + tid];
    for (int i = tid; i < Hf * Df; i += 128)
        sW2[i] = W2[i];
    if (tid < Hf) sb1[tid] = b1[tid];
    if (tid < Df) sb2[tid] = b2[tid];
    __syncthreads();

    int node = blockIdx.x * 128 + tid;
    if (node >= N) return;

    float4 fr[16];
    const float4* frow = (const float4*)(g_flow + (long long)node * Df);
    #pragma unroll
    for (int i = 0; i < 16; i++) fr[i] = frow[i];

    float acc[Df];
    #pragma unroll
    for (int i = 0; i < Df; i++) acc[i] = sb2[i];

    for (int j = 0; j < Hf; j++) {
        float h = sb1[j];
        const float4* w1 = (const float4*)(sW1T + j * W1T_STRIDE);
        #pragma unroll
        for (int i = 0; i < 16; i++) {
            float4 w = w1[i];
            h += fr[i].x * w.x + fr[i].y * w.y + fr[i].z * w.z + fr[i].w * w.w;
        }
        h = fmaxf(h, 0.0f);
        const float4* w2 = (const float4*)(sW2 + j * Df);
        #pragma unroll
        for (int i = 0; i < 16; i++) {
            float4 w = w2[i];
            acc[i * 4 + 0] += h * w.x;
            acc[i * 4 + 1] += h * w.y;
            acc[i * 4 + 2] += h * w.z;
            acc[i * 4 + 3] += h * w.w;
        }
    }

    float4* orow = (float4*)(out + (long long)node * Df);
    #pragma unroll
    for (int i = 0; i < 16; i++)
        orow[i] = make_float4(acc[i * 4], acc[i * 4 + 1], acc[i * 4 + 2], acc[i * 4 + 3]);
}

// ---------------------------------------------------------------------------
extern "C" void kernel_launch(void* const* d_in, const int* in_sizes, int n_in,
                              void* d_out, int out_size) {
    const int*   idx  = (const int*)d_in[0];
    const float* attr = (const float*)d_in[1];
    // num_nodes may or may not be materialized as an input
    int base = (n_in >= 7) ? 3 : 2;
    const float* W1 = (const float*)d_in[base + 0];
    const float* b1 = (const float*)d_in[base + 1];
    const float* W2 = (const float*)d_in[base + 2];
    const float* b2 = (const float*)d_in[base + 3];

    long long E = (long long)in_sizes[1] / Df;   // edge_attr is [E, 64]
    int N = out_size / Df;                        // output is [N, 64]

    void* flow_ptr = nullptr;
    cudaGetSymbolAddress(&flow_ptr, g_flow);
    cudaMemsetAsync(flow_ptr, 0, (size_t)N * Df * sizeof(float));

    probe_kernel<<<1, 256>>>(idx);

    long long total = E * 16;
    int blk = 256;
    unsigned nb = (unsigned)((total + blk - 1) / blk);
    scatter_kernel<<<nb, blk>>>(idx, (const float4*)attr, E);

    size_t smem = (size_t)(Hf * W1T_STRIDE + Hf * Df + Hf + Df) * sizeof(float);
    cudaFuncSetAttribute(mlp_kernel, cudaFuncAttributeMaxDynamicSharedMemorySize, (int)smem);
    mlp_kernel<<<(N + 127) / 128, 128, smem>>>(W1, b1, W2, b2, (float*)d_out, N);
}